// round 13
// baseline (speedup 1.0000x reference)
#include <cuda_runtime.h>

#define NPTS 8192
#define BINS 8192
#define BHINV (8192.0f / 12.0f)
#define BGLO -6.0f
#define QT 128                       // queries per nn block
#define TT 256                       // targets per tile
#define NTS (NPTS / TT)              // 32
#define NQB (NPTS / QT)              // 64
#define FULLMASK 0xffffffffu
#define BIG 3.0e38f
#define TOTQ (8 * NPTS)
#define EPSB 0.004f                  // covers bucket-internal disorder (2x width)

typedef unsigned long long ull;

__device__ float4 g_pts[8][NPTS];        // bucket-sorted-by-x quads (x,y,z,|p|^2)
__device__ unsigned g_hist[8][BINS];     // zero-init; re-zeroed by scan each run
__device__ int g_coff[8][BINS];          // scatter offsets (rebuilt each run)
__device__ float g_d2[TOTQ];             // per-query exact min d2 (rewritten)

__device__ __forceinline__ int bucket(float v) {
    int c = (int)floorf((v - BGLO) * BHINV);
    return min(max(c, 0), BINS - 1);
}
__device__ __forceinline__ ull pack2(float a, float b) {
    ull r;
    asm("mov.b64 %0, {%1, %2};" : "=l"(r) : "f"(a), "f"(b));
    return r;
}
// Proven packed step: d2-core(lo,hi) for 2 targets, fused mins.
__device__ __forceinline__ void step(float& ma, float& mb,
                                     ull qx, ull qy, ull qz,
                                     ull n0, ull n1, ull n2, ull cc) {
    asm("{\n\t"
        ".reg .b64 t;\n\t"
        ".reg .f32 lo, hi;\n\t"
        "fma.rn.f32x2 t, %2, %5, %8;\n\t"
        "fma.rn.f32x2 t, %3, %6, t;\n\t"
        "fma.rn.f32x2 t, %4, %7, t;\n\t"
        "mov.b64 {lo, hi}, t;\n\t"
        "min.f32 %0, %0, lo;\n\t"
        "min.f32 %1, %1, hi;\n\t"
        "}"
        : "+f"(ma), "+f"(mb)
        : "l"(qx), "l"(qy), "l"(qz), "l"(n0), "l"(n1), "l"(n2), "l"(cc));
}

// ---- Sort k1: histogram (64 blocks) ----------------------------------------
__global__ __launch_bounds__(256)
void hist_kernel(const float* __restrict__ p1, const float* __restrict__ p2) {
    const int db = blockIdx.x >> 3, chunk = blockIdx.x & 7;
    const float* __restrict__ P =
        ((db >> 2) ? p2 : p1) + (size_t)(db & 3) * NPTS * 3;
#pragma unroll
    for (int k = 0; k < 4; k++) {
        int i = chunk * 1024 + threadIdx.x + k * 256;
        atomicAdd(&g_hist[db][bucket(P[3 * i])], 1u);
    }
}

// ---- Sort k2: scan hist -> g_coff; zero hist; zero out[0] -------------------
__global__ __launch_bounds__(1024)
void scan_kernel(float* __restrict__ out) {
    __shared__ unsigned wtot[32];
    const int db = blockIdx.x, tid = threadIdx.x, lane = tid & 31, wid = tid >> 5;
    if (db == 0 && tid == 0) out[0] = 0.0f;

    const int base = tid * 8;
    unsigned h[8], loc[8], s = 0;
#pragma unroll
    for (int j = 0; j < 8; j++) {
        h[j] = g_hist[db][base + j];
        g_hist[db][base + j] = 0u;           // reset for next replay
        loc[j] = s; s += h[j];
    }
    unsigned v = s;
#pragma unroll
    for (int o = 1; o < 32; o <<= 1) {
        unsigned n = __shfl_up_sync(FULLMASK, v, o);
        if (lane >= o) v += n;
    }
    if (lane == 31) wtot[wid] = v;
    __syncthreads();
    if (tid < 32) {
        unsigned w = wtot[tid];
#pragma unroll
        for (int o = 1; o < 32; o <<= 1) {
            unsigned n = __shfl_up_sync(FULLMASK, w, o);
            if (tid >= o) w += n;
        }
        wtot[tid] = w;
    }
    __syncthreads();
    unsigned excl = v - s + (wid ? wtot[wid - 1] : 0u);
#pragma unroll
    for (int j = 0; j < 8; j++) g_coff[db][base + j] = (int)(excl + loc[j]);
}

// ---- Sort k3: scatter quads (64 blocks) -------------------------------------
__global__ __launch_bounds__(256)
void scatter_kernel(const float* __restrict__ p1, const float* __restrict__ p2) {
    const int db = blockIdx.x >> 3, chunk = blockIdx.x & 7;
    const float* __restrict__ P =
        ((db >> 2) ? p2 : p1) + (size_t)(db & 3) * NPTS * 3;
#pragma unroll
    for (int k = 0; k < 4; k++) {
        int i = chunk * 1024 + threadIdx.x + k * 256;
        float x = P[3 * i], y = P[3 * i + 1], z = P[3 * i + 2];
        int pos = atomicAdd(&g_coff[db][bucket(x)], 1);
        g_pts[db][pos] = make_float4(x, y, z, x * x + y * y + z * z);
    }
}

// ---- NN: one block owns 128 queries. Bound phase -> survivor tile range ----
// ---- -> fixed FFMA2 scans. No atomics, no separate bound kernel. -----------
__global__ __launch_bounds__(QT)
void nn_kernel() {
    __shared__ __align__(16) char s_buf[4096];   // union: window / packed tile
    __shared__ float s_red[4];
    __shared__ int s_range[2];

    float4* s_w = (float4*)s_buf;                // 256 float4
    ull (*s_t)[4] = (ull(*)[4])s_buf;            // 128 packed pairs

    const int tid = threadIdx.x, lane = tid & 31, wid = tid >> 5;
    const int db = blockIdx.y, qb = blockIdx.x;
    const float4* __restrict__ Q = g_pts[db];
    const float4* __restrict__ T = g_pts[db ^ 4];

    const int qbase = qb * QT;
    const float4 q = Q[qbase + tid];
    const float qsq = q.w;
    const float m2x = -2.f * q.x, m2y = -2.f * q.y, m2z = -2.f * q.z;

    // ---- Phase 1: stage 256-target rank window; per-thread upper bound ----
    const int ws = min(max(qbase + QT / 2 - 128, 0), NPTS - 256);
    s_w[tid]      = T[ws + tid];
    s_w[tid + QT] = T[ws + tid + QT];
    __syncthreads();

    float a0 = BIG, a1 = BIG, a2 = BIG, a3 = BIG;
#pragma unroll 4
    for (int j = 0; j < 256; j += 4) {           // warp-uniform LDS broadcast
        float4 t0 = s_w[j], t1 = s_w[j + 1], t2 = s_w[j + 2], t3 = s_w[j + 3];
        a0 = fminf(a0, fmaf(m2x, t0.x, fmaf(m2y, t0.y, fmaf(m2z, t0.z, t0.w))));
        a1 = fminf(a1, fmaf(m2x, t1.x, fmaf(m2y, t1.y, fmaf(m2z, t1.z, t1.w))));
        a2 = fminf(a2, fmaf(m2x, t2.x, fmaf(m2y, t2.y, fmaf(m2z, t2.z, t2.w))));
        a3 = fminf(a3, fmaf(m2x, t3.x, fmaf(m2y, t3.y, fmaf(m2z, t3.z, t3.w))));
    }
    const float ubv = fminf(fminf(a0, a1), fminf(a2, a3));  // running min core

    float dm = fmaxf(ubv + qsq, 0.0f);
#pragma unroll
    for (int o = 16; o; o >>= 1) dm = fmaxf(dm, __shfl_xor_sync(FULLMASK, dm, o));
    if (lane == 0) s_red[wid] = dm;
    __syncthreads();
    if (tid == 0) {
        float dmax = fmaxf(fmaxf(s_red[0], s_red[1]), fmaxf(s_red[2], s_red[3]));
        const float R = sqrtf(dmax) * 1.0005f + 1e-4f + EPSB;
        const float qlo = Q[qbase].x - R - EPSB;
        const float qhi = Q[qbase + QT - 1].x + R + EPSB;
        int lo = 0;
        while (lo < NTS - 1 && T[(lo + 1) * TT - 1].x < qlo) lo++;
        int hi = NTS - 1;
        while (hi > 0 && T[hi * TT].x > qhi) hi--;
        s_range[0] = lo; s_range[1] = hi;
    }
    __syncthreads();
    const int lo = s_range[0], hi = s_range[1];

    // ---- Phase 2: fixed FFMA2 scan over survivor tiles ----
    const ull qx2 = pack2(q.x, q.x), qy2 = pack2(q.y, q.y), qz2 = pack2(q.z, q.z);
    float ma = ubv, mb = BIG;

    for (int ts = lo; ts <= hi; ts++) {
        __syncthreads();                         // prior reads done
        {
            float4 ta = T[ts * TT + 2 * tid];
            float4 tc = T[ts * TT + 2 * tid + 1];
            ulonglong2* d = (ulonglong2*)s_t[tid];
            d[0] = make_ulonglong2(pack2(-2.0f * ta.x, -2.0f * tc.x),
                                   pack2(-2.0f * ta.y, -2.0f * tc.y));
            d[1] = make_ulonglong2(pack2(-2.0f * ta.z, -2.0f * tc.z),
                                   pack2(ta.w, tc.w));
        }
        __syncthreads();

        const ulonglong2* sm = (const ulonglong2*)&s_t[0][0];
#pragma unroll 4
        for (int j = 0; j < TT / 2; j++) {
            ulonglong2 v0 = sm[2 * j];           // (n0,n1) LDS.128 broadcast
            ulonglong2 v1 = sm[2 * j + 1];       // (n2,cc)
            step(ma, mb, qx2, qy2, qz2, v0.x, v0.y, v1.x, v1.y);
        }
    }

    g_d2[db * NPTS + qbase + tid] = fminf(ma, mb) + qsq;   // exact min d2
}

// ---- Finish: sum all d2 -> out[0] -------------------------------------------
__global__ __launch_bounds__(256)
void finish_kernel(float* __restrict__ out) {
    const int gid = blockIdx.x * 256 + threadIdx.x;
    float v = g_d2[gid];
    __shared__ float sred[8];
#pragma unroll
    for (int o = 16; o; o >>= 1) v += __shfl_down_sync(FULLMASK, v, o);
    if ((threadIdx.x & 31) == 0) sred[threadIdx.x >> 5] = v;
    __syncthreads();
    if (threadIdx.x == 0) {
        float t = 0.f;
#pragma unroll
        for (int i = 0; i < 8; i++) t += sred[i];
        atomicAdd(out, t);
    }
}

extern "C" void kernel_launch(void* const* d_in, const int* in_sizes, int n_in,
                              void* d_out, int out_size) {
    const float* p1 = (const float*)d_in[0];
    const float* p2 = (const float*)d_in[1];
    float* out = (float*)d_out;

    hist_kernel<<<64, 256>>>(p1, p2);
    scan_kernel<<<8, 1024>>>(out);
    scatter_kernel<<<64, 256>>>(p1, p2);
    nn_kernel<<<dim3(NQB, 8), QT>>>();
    finish_kernel<<<TOTQ / 256, 256>>>(out);
}

// round 14
// speedup vs baseline: 1.5181x; 1.5181x over previous
#include <cuda_runtime.h>

#define NPTS 8192
#define BINS 8192
#define BHINV (8192.0f / 12.0f)
#define BGLO -6.0f
#define TQ 128                       // queries per tile (prune granularity)
#define TT 256                       // targets per tile
#define NQT (NPTS / TQ)              // 64
#define NTS (NPTS / TT)              // 32
#define FULLMASK 0xffffffffu
#define BIG 3.0e38f
#define TOTQ (8 * NPTS)
#define EPSB 0.002f                  // > bucket width (12/8192): sort disorder

typedef unsigned long long ull;

__device__ float4 g_pts[8][NPTS];        // bucket-sorted-by-x quads (x,y,z,|p|^2)
__device__ unsigned g_hist[8][BINS];     // zero-init; re-zeroed by scan each run
__device__ int g_coff[8][BINS];          // scatter offsets (rebuilt each run)
__device__ float g_dmax[8][NQT];         // per-query-tile d2 upper bound
__device__ unsigned g_key[TOTQ];         // enckey; 0 identity; reset by finish

__device__ __forceinline__ int bucket(float v) {
    int c = (int)floorf((v - BGLO) * BHINV);
    return min(max(c, 0), BINS - 1);
}
__device__ __forceinline__ unsigned enckey(float f) {
    unsigned u = __float_as_uint(f);
    u = (u & 0x80000000u) ? ~u : (u | 0x80000000u);
    return ~u;
}
__device__ __forceinline__ float deckey(unsigned k) {
    unsigned u = ~k;
    return __uint_as_float((u & 0x80000000u) ? (u & 0x7FFFFFFFu) : ~u);
}
__device__ __forceinline__ ull pack2(float a, float b) {
    ull r;
    asm("mov.b64 %0, {%1, %2};" : "=l"(r) : "f"(a), "f"(b));
    return r;
}
// Proven packed step: d2-core(lo,hi) for 2 targets, fused mins.
__device__ __forceinline__ void step(float& ma, float& mb,
                                     ull qx, ull qy, ull qz,
                                     ull n0, ull n1, ull n2, ull cc) {
    asm("{\n\t"
        ".reg .b64 t;\n\t"
        ".reg .f32 lo, hi;\n\t"
        "fma.rn.f32x2 t, %2, %5, %8;\n\t"
        "fma.rn.f32x2 t, %3, %6, t;\n\t"
        "fma.rn.f32x2 t, %4, %7, t;\n\t"
        "mov.b64 {lo, hi}, t;\n\t"
        "min.f32 %0, %0, lo;\n\t"
        "min.f32 %1, %1, hi;\n\t"
        "}"
        : "+f"(ma), "+f"(mb)
        : "l"(qx), "l"(qy), "l"(qz), "l"(n0), "l"(n1), "l"(n2), "l"(cc));
}

// ---- Sort k1: histogram (64 blocks) ----------------------------------------
__global__ __launch_bounds__(256)
void hist_kernel(const float* __restrict__ p1, const float* __restrict__ p2) {
    const int db = blockIdx.x >> 3, chunk = blockIdx.x & 7;
    const float* __restrict__ P =
        ((db >> 2) ? p2 : p1) + (size_t)(db & 3) * NPTS * 3;
#pragma unroll
    for (int k = 0; k < 4; k++) {
        int i = chunk * 1024 + threadIdx.x + k * 256;
        atomicAdd(&g_hist[db][bucket(P[3 * i])], 1u);
    }
}

// ---- Sort k2: scan hist -> g_coff; zero hist; zero out[0] -------------------
__global__ __launch_bounds__(1024)
void scan_kernel(float* __restrict__ out) {
    __shared__ unsigned wtot[32];
    const int db = blockIdx.x, tid = threadIdx.x, lane = tid & 31, wid = tid >> 5;
    if (db == 0 && tid == 0) out[0] = 0.0f;

    const int base = tid * 8;
    unsigned h[8], loc[8], s = 0;
#pragma unroll
    for (int j = 0; j < 8; j++) {
        h[j] = g_hist[db][base + j];
        g_hist[db][base + j] = 0u;           // reset for next replay
        loc[j] = s; s += h[j];
    }
    unsigned v = s;
#pragma unroll
    for (int o = 1; o < 32; o <<= 1) {
        unsigned n = __shfl_up_sync(FULLMASK, v, o);
        if (lane >= o) v += n;
    }
    if (lane == 31) wtot[wid] = v;
    __syncthreads();
    if (tid < 32) {
        unsigned w = wtot[tid];
#pragma unroll
        for (int o = 1; o < 32; o <<= 1) {
            unsigned n = __shfl_up_sync(FULLMASK, w, o);
            if (tid >= o) w += n;
        }
        wtot[tid] = w;
    }
    __syncthreads();
    unsigned excl = v - s + (wid ? wtot[wid - 1] : 0u);
#pragma unroll
    for (int j = 0; j < 8; j++) g_coff[db][base + j] = (int)(excl + loc[j]);
}

// ---- Sort k3: scatter quads (64 blocks) -------------------------------------
__global__ __launch_bounds__(256)
void scatter_kernel(const float* __restrict__ p1, const float* __restrict__ p2) {
    const int db = blockIdx.x >> 3, chunk = blockIdx.x & 7;
    const float* __restrict__ P =
        ((db >> 2) ? p2 : p1) + (size_t)(db & 3) * NPTS * 3;
#pragma unroll
    for (int k = 0; k < 4; k++) {
        int i = chunk * 1024 + threadIdx.x + k * 256;
        float x = P[3 * i], y = P[3 * i + 1], z = P[3 * i + 2];
        int pos = atomicAdd(&g_coff[db][bucket(x)], 1);
        g_pts[db][pos] = make_float4(x, y, z, x * x + y * y + z * z);
    }
}

// ---- Pass A: per-128-query-tile upper bound from smem-staged 256 window -----
__global__ __launch_bounds__(TQ)
void bound_kernel() {
    __shared__ __align__(16) float4 s_w[256];    // 4 KB window
    __shared__ float sred[TQ / 32];
    const int tid = threadIdx.x, lane = tid & 31, wid = tid >> 5;
    const int qt = blockIdx.x, db = blockIdx.y;
    const float4* __restrict__ Q = g_pts[db];
    const float4* __restrict__ T = g_pts[db ^ 4];

    const int ws = min(max(qt * TQ + TQ / 2 - 128, 0), NPTS - 256);
    s_w[tid]      = T[ws + tid];                 // coalesced stage
    s_w[tid + TQ] = T[ws + tid + TQ];
    const float4 q = Q[qt * TQ + tid];
    const float m2x = -2.f * q.x, m2y = -2.f * q.y, m2z = -2.f * q.z;
    __syncthreads();

    float a0 = BIG, a1 = BIG, a2 = BIG, a3 = BIG;
#pragma unroll 4
    for (int j = 0; j < 256; j += 4) {           // warp-uniform LDS broadcast
        float4 t0 = s_w[j], t1 = s_w[j + 1], t2 = s_w[j + 2], t3 = s_w[j + 3];
        a0 = fminf(a0, fmaf(m2x, t0.x, fmaf(m2y, t0.y, fmaf(m2z, t0.z, t0.w))));
        a1 = fminf(a1, fmaf(m2x, t1.x, fmaf(m2y, t1.y, fmaf(m2z, t1.z, t1.w))));
        a2 = fminf(a2, fmaf(m2x, t2.x, fmaf(m2y, t2.y, fmaf(m2z, t2.z, t2.w))));
        a3 = fminf(a3, fmaf(m2x, t3.x, fmaf(m2y, t3.y, fmaf(m2z, t3.z, t3.w))));
    }
    float dm = fmaxf(fminf(fminf(a0, a1), fminf(a2, a3)) + q.w, 0.0f);

#pragma unroll
    for (int o = 16; o; o >>= 1) dm = fmaxf(dm, __shfl_xor_sync(FULLMASK, dm, o));
    if (lane == 0) sred[wid] = dm;
    __syncthreads();
    if (tid == 0) {
        float m = 0.f;
#pragma unroll
        for (int i = 0; i < TQ / 32; i++) m = fmaxf(m, sred[i]);
        g_dmax[db][qt] = m;
    }
}

// ---- Pass B: FFMA2 tile loop, block-level x-gap prune (bucket-disorder safe) -
__global__ __launch_bounds__(TQ)
void tile_kernel() {
    const int qt = blockIdx.x >> 5, ts = blockIdx.x & 31;
    const int db = blockIdx.y;
    const float4* __restrict__ Q = g_pts[db];
    const float4* __restrict__ T = g_pts[db ^ 4];

    // Prune with 2*EPSB margin for bucket-internal disorder.
    {
        const float qlo = Q[qt * TQ].x, qhi = Q[qt * TQ + TQ - 1].x;
        const float tlo = T[ts * TT].x, thi = T[ts * TT + TT - 1].x;
        const float gap = fmaxf(0.f,
            fmaxf(tlo - qhi, qlo - thi) - 2.0f * EPSB);
        if (gap * gap > g_dmax[db][qt] * 1.0001f + 1e-6f) return;
    }

    __shared__ __align__(16) ull s_t[TT / 2][4];     // 4 KB packed pairs
    const int tid = threadIdx.x;

    // Stage target tile: per pair -> (n0,n1,n2,cc) packed f32x2.
    {
        float4 ta = T[ts * TT + 2 * tid];
        float4 tc = T[ts * TT + 2 * tid + 1];
        ulonglong2* d = (ulonglong2*)s_t[tid];
        d[0] = make_ulonglong2(pack2(-2.0f * ta.x, -2.0f * tc.x),
                               pack2(-2.0f * ta.y, -2.0f * tc.y));
        d[1] = make_ulonglong2(pack2(-2.0f * ta.z, -2.0f * tc.z),
                               pack2(ta.w, tc.w));
    }

    const float4 q = Q[qt * TQ + tid];
    const ull qx = pack2(q.x, q.x), qy = pack2(q.y, q.y), qz = pack2(q.z, q.z);
    float ma = BIG, mb = BIG;
    __syncthreads();

    const ulonglong2* sm = (const ulonglong2*)&s_t[0][0];
#pragma unroll 4
    for (int j = 0; j < TT / 2; j++) {
        ulonglong2 v0 = sm[2 * j];       // (n0,n1) LDS.128 broadcast
        ulonglong2 v1 = sm[2 * j + 1];   // (n2,cc)
        step(ma, mb, qx, qy, qz, v0.x, v0.y, v1.x, v1.y);
    }

    atomicMax(&g_key[db * NPTS + qt * TQ + tid], enckey(fminf(ma, mb)));
}

// ---- Finish: add |q|^2, reduce, atomicAdd; reset keys ------------------------
__global__ __launch_bounds__(256)
void finish_kernel(float* __restrict__ out) {
    const int gid = blockIdx.x * 256 + threadIdx.x;
    const int db = gid >> 13, qi = gid & (NPTS - 1);
    float v = deckey(g_key[gid]) + g_pts[db][qi].w;
    g_key[gid] = 0u;

    __shared__ float sred[8];
#pragma unroll
    for (int o = 16; o; o >>= 1) v += __shfl_down_sync(FULLMASK, v, o);
    if ((threadIdx.x & 31) == 0) sred[threadIdx.x >> 5] = v;
    __syncthreads();
    if (threadIdx.x == 0) {
        float t = 0.f;
#pragma unroll
        for (int i = 0; i < 8; i++) t += sred[i];
        atomicAdd(out, t);
    }
}

extern "C" void kernel_launch(void* const* d_in, const int* in_sizes, int n_in,
                              void* d_out, int out_size) {
    const float* p1 = (const float*)d_in[0];
    const float* p2 = (const float*)d_in[1];
    float* out = (float*)d_out;

    hist_kernel<<<64, 256>>>(p1, p2);
    scan_kernel<<<8, 1024>>>(out);
    scatter_kernel<<<64, 256>>>(p1, p2);
    bound_kernel<<<dim3(NQT, 8), TQ>>>();
    tile_kernel<<<dim3(NQT * NTS, 8), TQ>>>();
    finish_kernel<<<TOTQ / 256, 256>>>(out);
}

// round 15
// speedup vs baseline: 2.1544x; 1.4191x over previous
#include <cuda_runtime.h>

#define NPTS 8192
#define BINS 8192
#define BHINV (8192.0f / 12.0f)
#define BGLO -6.0f
#define TQ 256                       // queries per tile
#define TT 256                       // targets per tile
#define NQT (NPTS / TQ)              // 32
#define NTS (NPTS / TT)              // 32
#define PB_THREADS 128
#define FULLMASK 0xffffffffu
#define BIG 3.0e38f
#define TOTQ (8 * NPTS)
#define EPSB 0.002f                  // > bucket width (12/8192): sort disorder

typedef unsigned long long ull;

__device__ float4 g_pts[8][NPTS];        // bucket-sorted-by-x quads (x,y,z,|p|^2)
__device__ unsigned g_hist[8][BINS];     // zero-init; re-zeroed by scan each run
__device__ int g_coff[8][BINS];          // scatter offsets (rebuilt each run)
__device__ float g_dmax[8][NQT];         // per-256-query-tile d2 bound
__device__ float g_dmaxw[8][NQT * 8];    // per-32-query-warp d2 bound
__device__ unsigned g_key[TOTQ];         // enckey; 0 identity; reset by finish

__device__ __forceinline__ int bucket(float v) {
    int c = (int)floorf((v - BGLO) * BHINV);
    return min(max(c, 0), BINS - 1);
}
__device__ __forceinline__ unsigned enckey(float f) {
    unsigned u = __float_as_uint(f);
    u = (u & 0x80000000u) ? ~u : (u | 0x80000000u);
    return ~u;
}
__device__ __forceinline__ float deckey(unsigned k) {
    unsigned u = ~k;
    return __uint_as_float((u & 0x80000000u) ? (u & 0x7FFFFFFFu) : ~u);
}
__device__ __forceinline__ ull pack2(float a, float b) {
    ull r;
    asm("mov.b64 %0, {%1, %2};" : "=l"(r) : "f"(a), "f"(b));
    return r;
}
// Proven packed step: d2-core(lo,hi) for 2 targets, fused mins.
__device__ __forceinline__ void step(float& ma, float& mb,
                                     ull qx, ull qy, ull qz,
                                     ull n0, ull n1, ull n2, ull cc) {
    asm("{\n\t"
        ".reg .b64 t;\n\t"
        ".reg .f32 lo, hi;\n\t"
        "fma.rn.f32x2 t, %2, %5, %8;\n\t"
        "fma.rn.f32x2 t, %3, %6, t;\n\t"
        "fma.rn.f32x2 t, %4, %7, t;\n\t"
        "mov.b64 {lo, hi}, t;\n\t"
        "min.f32 %0, %0, lo;\n\t"
        "min.f32 %1, %1, hi;\n\t"
        "}"
        : "+f"(ma), "+f"(mb)
        : "l"(qx), "l"(qy), "l"(qz), "l"(n0), "l"(n1), "l"(n2), "l"(cc));
}

// ---- Sort k1: histogram (64 blocks) ----------------------------------------
__global__ __launch_bounds__(256)
void hist_kernel(const float* __restrict__ p1, const float* __restrict__ p2) {
    const int db = blockIdx.x >> 3, chunk = blockIdx.x & 7;
    const float* __restrict__ P =
        ((db >> 2) ? p2 : p1) + (size_t)(db & 3) * NPTS * 3;
#pragma unroll
    for (int k = 0; k < 4; k++) {
        int i = chunk * 1024 + threadIdx.x + k * 256;
        atomicAdd(&g_hist[db][bucket(P[3 * i])], 1u);
    }
}

// ---- Sort k2: scan hist -> g_coff; zero hist; zero out[0] -------------------
__global__ __launch_bounds__(1024)
void scan_kernel(float* __restrict__ out) {
    __shared__ unsigned wtot[32];
    const int db = blockIdx.x, tid = threadIdx.x, lane = tid & 31, wid = tid >> 5;
    if (db == 0 && tid == 0) out[0] = 0.0f;

    const int base = tid * 8;
    unsigned h[8], loc[8], s = 0;
#pragma unroll
    for (int j = 0; j < 8; j++) {
        h[j] = g_hist[db][base + j];
        g_hist[db][base + j] = 0u;           // reset for next replay
        loc[j] = s; s += h[j];
    }
    unsigned v = s;
#pragma unroll
    for (int o = 1; o < 32; o <<= 1) {
        unsigned n = __shfl_up_sync(FULLMASK, v, o);
        if (lane >= o) v += n;
    }
    if (lane == 31) wtot[wid] = v;
    __syncthreads();
    if (tid < 32) {
        unsigned w = wtot[tid];
#pragma unroll
        for (int o = 1; o < 32; o <<= 1) {
            unsigned n = __shfl_up_sync(FULLMASK, w, o);
            if (tid >= o) w += n;
        }
        wtot[tid] = w;
    }
    __syncthreads();
    unsigned excl = v - s + (wid ? wtot[wid - 1] : 0u);
#pragma unroll
    for (int j = 0; j < 8; j++) g_coff[db][base + j] = (int)(excl + loc[j]);
}

// ---- Sort k3: scatter quads (64 blocks) -------------------------------------
__global__ __launch_bounds__(256)
void scatter_kernel(const float* __restrict__ p1, const float* __restrict__ p2) {
    const int db = blockIdx.x >> 3, chunk = blockIdx.x & 7;
    const float* __restrict__ P =
        ((db >> 2) ? p2 : p1) + (size_t)(db & 3) * NPTS * 3;
#pragma unroll
    for (int k = 0; k < 4; k++) {
        int i = chunk * 1024 + threadIdx.x + k * 256;
        float x = P[3 * i], y = P[3 * i + 1], z = P[3 * i + 2];
        int pos = atomicAdd(&g_coff[db][bucket(x)], 1);
        g_pts[db][pos] = make_float4(x, y, z, x * x + y * y + z * z);
    }
}

// ---- Pass A: per-tile AND per-warp d2 bounds from smem-staged 256 window ----
__global__ __launch_bounds__(TQ)
void bound_kernel() {
    __shared__ __align__(16) float4 s_w[256];    // 4 KB window
    __shared__ float sred[TQ / 32];
    const int tid = threadIdx.x, lane = tid & 31, wid = tid >> 5;
    const int qt = blockIdx.x, db = blockIdx.y;
    const float4* __restrict__ Q = g_pts[db];
    const float4* __restrict__ T = g_pts[db ^ 4];

    const int ws = min(max(qt * TQ + TQ / 2 - 128, 0), NPTS - 256);
    s_w[tid] = T[ws + tid];                      // coalesced stage
    const float4 q = Q[qt * TQ + tid];
    const float m2x = -2.f * q.x, m2y = -2.f * q.y, m2z = -2.f * q.z;
    __syncthreads();

    float a0 = BIG, a1 = BIG, a2 = BIG, a3 = BIG;
#pragma unroll 4
    for (int j = 0; j < 256; j += 4) {           // warp-uniform LDS broadcast
        float4 t0 = s_w[j], t1 = s_w[j + 1], t2 = s_w[j + 2], t3 = s_w[j + 3];
        a0 = fminf(a0, fmaf(m2x, t0.x, fmaf(m2y, t0.y, fmaf(m2z, t0.z, t0.w))));
        a1 = fminf(a1, fmaf(m2x, t1.x, fmaf(m2y, t1.y, fmaf(m2z, t1.z, t1.w))));
        a2 = fminf(a2, fmaf(m2x, t2.x, fmaf(m2y, t2.y, fmaf(m2z, t2.z, t2.w))));
        a3 = fminf(a3, fmaf(m2x, t3.x, fmaf(m2y, t3.y, fmaf(m2z, t3.z, t3.w))));
    }
    float dm = fmaxf(fminf(fminf(a0, a1), fminf(a2, a3)) + q.w, 0.0f);

#pragma unroll
    for (int o = 16; o; o >>= 1) dm = fmaxf(dm, __shfl_xor_sync(FULLMASK, dm, o));
    if (lane == 0) {
        sred[wid] = dm;
        g_dmaxw[db][qt * 8 + wid] = dm;          // per-32-query-warp bound
    }
    __syncthreads();
    if (tid == 0) {
        float m = 0.f;
#pragma unroll
        for (int i = 0; i < TQ / 32; i++) m = fmaxf(m, sred[i]);
        g_dmax[db][qt] = m;
    }
}

// ---- Pass B: FFMA2 tile loop; block-level AND warp-level x-gap pruning ------
__global__ __launch_bounds__(PB_THREADS)
void tile_kernel() {
    const int qt = blockIdx.x >> 5, ts = blockIdx.x & 31;
    const int db = blockIdx.y;
    const float4* __restrict__ Q = g_pts[db];
    const float4* __restrict__ T = g_pts[db ^ 4];

    const float tlo = T[ts * TT].x, thi = T[ts * TT + TT - 1].x;

    // Block-level prune (endpoint x's; 2*EPSB covers bucket disorder).
    {
        const float qlo = Q[qt * TQ].x, qhi = Q[qt * TQ + TQ - 1].x;
        const float gap = fmaxf(0.f, fmaxf(tlo - qhi, qlo - thi) - 2.0f * EPSB);
        if (gap * gap > g_dmax[db][qt] * 1.0001f + 1e-6f) return;
    }

    __shared__ __align__(16) ull s_t[TT / 2][4];     // 4 KB packed pairs
    const int tid = threadIdx.x, lane = tid & 31, wid = tid >> 5;

    // Stage target tile: per pair -> (n0,n1,n2,cc) packed f32x2.
    {
        float4 ta = T[ts * TT + 2 * tid];
        float4 tc = T[ts * TT + 2 * tid + 1];
        ulonglong2* d = (ulonglong2*)s_t[tid];
        d[0] = make_ulonglong2(pack2(-2.0f * ta.x, -2.0f * tc.x),
                               pack2(-2.0f * ta.y, -2.0f * tc.y));
        d[1] = make_ulonglong2(pack2(-2.0f * ta.z, -2.0f * tc.z),
                               pack2(ta.w, tc.w));
    }

    // Warp owns 64 contiguous queries: q0 = 2*tid, q1 = 2*tid+1.
    const float4 qa = Q[qt * TQ + 2 * tid];
    const float4 qb = Q[qt * TQ + 2 * tid + 1];
    __syncthreads();

    // Warp-level prune: exact query x-range via shuffle reduction.
    {
        float xmn = fminf(qa.x, qb.x), xmx = fmaxf(qa.x, qb.x);
#pragma unroll
        for (int o = 16; o; o >>= 1) {
            xmn = fminf(xmn, __shfl_xor_sync(FULLMASK, xmn, o));
            xmx = fmaxf(xmx, __shfl_xor_sync(FULLMASK, xmx, o));
        }
        const float wd = fmaxf(g_dmaxw[db][qt * 8 + wid * 2],
                               g_dmaxw[db][qt * 8 + wid * 2 + 1]);
        const float gap = fmaxf(0.f, fmaxf(tlo - xmx, xmn - thi) - EPSB);
        if (gap * gap > wd * 1.0001f + 1e-6f) return;   // whole warp certified
    }

    const ull qx0 = pack2(qa.x, qa.x), qy0 = pack2(qa.y, qa.y), qz0 = pack2(qa.z, qa.z);
    const ull qx1 = pack2(qb.x, qb.x), qy1 = pack2(qb.y, qb.y), qz1 = pack2(qb.z, qb.z);
    float ma0 = BIG, mb0 = BIG, ma1 = BIG, mb1 = BIG;

    const ulonglong2* sm = (const ulonglong2*)&s_t[0][0];
#pragma unroll 4
    for (int j = 0; j < TT / 2; j++) {
        ulonglong2 v0 = sm[2 * j];       // (n0,n1) LDS.128 broadcast
        ulonglong2 v1 = sm[2 * j + 1];   // (n2,cc)
        step(ma0, mb0, qx0, qy0, qz0, v0.x, v0.y, v1.x, v1.y);
        step(ma1, mb1, qx1, qy1, qz1, v0.x, v0.y, v1.x, v1.y);
    }

    unsigned* gk = g_key + db * NPTS + qt * TQ;
    atomicMax(&gk[2 * tid],     enckey(fminf(ma0, mb0)));
    atomicMax(&gk[2 * tid + 1], enckey(fminf(ma1, mb1)));
}

// ---- Finish: add |q|^2, reduce, atomicAdd; reset keys ------------------------
__global__ __launch_bounds__(256)
void finish_kernel(float* __restrict__ out) {
    const int gid = blockIdx.x * 256 + threadIdx.x;
    const int db = gid >> 13, qi = gid & (NPTS - 1);
    float v = deckey(g_key[gid]) + g_pts[db][qi].w;
    g_key[gid] = 0u;

    __shared__ float sred[8];
#pragma unroll
    for (int o = 16; o; o >>= 1) v += __shfl_down_sync(FULLMASK, v, o);
    if ((threadIdx.x & 31) == 0) sred[threadIdx.x >> 5] = v;
    __syncthreads();
    if (threadIdx.x == 0) {
        float t = 0.f;
#pragma unroll
        for (int i = 0; i < 8; i++) t += sred[i];
        atomicAdd(out, t);
    }
}

extern "C" void kernel_launch(void* const* d_in, const int* in_sizes, int n_in,
                              void* d_out, int out_size) {
    const float* p1 = (const float*)d_in[0];
    const float* p2 = (const float*)d_in[1];
    float* out = (float*)d_out;

    hist_kernel<<<64, 256>>>(p1, p2);
    scan_kernel<<<8, 1024>>>(out);
    scatter_kernel<<<64, 256>>>(p1, p2);
    bound_kernel<<<dim3(NQT, 8), TQ>>>();
    tile_kernel<<<dim3(NQT * NTS, 8), PB_THREADS>>>();
    finish_kernel<<<TOTQ / 256, 256>>>(out);
}

// round 16
// speedup vs baseline: 2.2030x; 1.0226x over previous
#include <cuda_runtime.h>

#define NPTS 8192
#define BINS 8192
#define BHINV (8192.0f / 12.0f)
#define BGLO -6.0f
#define TQ 256                       // queries per tile
#define TT 256                       // targets per tile
#define NQT (NPTS / TQ)              // 32
#define NTS (NPTS / TT)              // 32
#define PB_THREADS 128
#define FULLMASK 0xffffffffu
#define BIG 3.0e38f
#define TOTQ (8 * NPTS)
#define EPSB 0.002f                  // > bucket width (12/8192): sort disorder

typedef unsigned long long ull;

__device__ float4 g_pts[8][NPTS];        // bucket-sorted-by-x quads (x,y,z,|p|^2)
__device__ unsigned g_hist[8][BINS];     // zero-init; re-zeroed by scan each run
__device__ int g_coff[8][BINS];          // scatter offsets (rebuilt each run)
__device__ int g_dmax[8][NQT];           // per-256-query-tile d2 bound (float bits)
__device__ float g_dmaxw[8][NQT * 8];    // per-32-query-warp d2 bound
__device__ unsigned g_key[TOTQ];         // enckey; 0 identity; reset by finish

__device__ __forceinline__ int bucket(float v) {
    int c = (int)floorf((v - BGLO) * BHINV);
    return min(max(c, 0), BINS - 1);
}
__device__ __forceinline__ unsigned enckey(float f) {
    unsigned u = __float_as_uint(f);
    u = (u & 0x80000000u) ? ~u : (u | 0x80000000u);
    return ~u;
}
__device__ __forceinline__ float deckey(unsigned k) {
    unsigned u = ~k;
    return __uint_as_float((u & 0x80000000u) ? (u & 0x7FFFFFFFu) : ~u);
}
__device__ __forceinline__ ull pack2(float a, float b) {
    ull r;
    asm("mov.b64 %0, {%1, %2};" : "=l"(r) : "f"(a), "f"(b));
    return r;
}
// Proven packed step: d2-core(lo,hi) for 2 targets, fused mins.
__device__ __forceinline__ void step(float& ma, float& mb,
                                     ull qx, ull qy, ull qz,
                                     ull n0, ull n1, ull n2, ull cc) {
    asm("{\n\t"
        ".reg .b64 t;\n\t"
        ".reg .f32 lo, hi;\n\t"
        "fma.rn.f32x2 t, %2, %5, %8;\n\t"
        "fma.rn.f32x2 t, %3, %6, t;\n\t"
        "fma.rn.f32x2 t, %4, %7, t;\n\t"
        "mov.b64 {lo, hi}, t;\n\t"
        "min.f32 %0, %0, lo;\n\t"
        "min.f32 %1, %1, hi;\n\t"
        "}"
        : "+f"(ma), "+f"(mb)
        : "l"(qx), "l"(qy), "l"(qz), "l"(n0), "l"(n1), "l"(n2), "l"(cc));
}

// ---- Sort k1: histogram (128 blocks) ----------------------------------------
__global__ __launch_bounds__(256)
void hist_kernel(const float* __restrict__ p1, const float* __restrict__ p2) {
    const int db = blockIdx.x >> 4, chunk = blockIdx.x & 15;
    const float* __restrict__ P =
        ((db >> 2) ? p2 : p1) + (size_t)(db & 3) * NPTS * 3;
#pragma unroll
    for (int k = 0; k < 2; k++) {
        int i = chunk * 512 + threadIdx.x + k * 256;
        atomicAdd(&g_hist[db][bucket(P[3 * i])], 1u);
    }
}

// ---- Sort k2: scan hist -> g_coff; zero hist/dmax; zero out[0] ---------------
__global__ __launch_bounds__(1024)
void scan_kernel(float* __restrict__ out) {
    __shared__ unsigned wtot[32];
    const int db = blockIdx.x, tid = threadIdx.x, lane = tid & 31, wid = tid >> 5;
    if (db == 0 && tid == 0) out[0] = 0.0f;
    if (tid < NQT) g_dmax[db][tid] = 0;

    const int base = tid * 8;
    unsigned h[8], loc[8], s = 0;
#pragma unroll
    for (int j = 0; j < 8; j++) {
        h[j] = g_hist[db][base + j];
        g_hist[db][base + j] = 0u;           // reset for next replay
        loc[j] = s; s += h[j];
    }
    unsigned v = s;
#pragma unroll
    for (int o = 1; o < 32; o <<= 1) {
        unsigned n = __shfl_up_sync(FULLMASK, v, o);
        if (lane >= o) v += n;
    }
    if (lane == 31) wtot[wid] = v;
    __syncthreads();
    if (tid < 32) {
        unsigned w = wtot[tid];
#pragma unroll
        for (int o = 1; o < 32; o <<= 1) {
            unsigned n = __shfl_up_sync(FULLMASK, w, o);
            if (tid >= o) w += n;
        }
        wtot[tid] = w;
    }
    __syncthreads();
    unsigned excl = v - s + (wid ? wtot[wid - 1] : 0u);
#pragma unroll
    for (int j = 0; j < 8; j++) g_coff[db][base + j] = (int)(excl + loc[j]);
}

// ---- Sort k3: scatter quads (128 blocks) -------------------------------------
__global__ __launch_bounds__(256)
void scatter_kernel(const float* __restrict__ p1, const float* __restrict__ p2) {
    const int db = blockIdx.x >> 4, chunk = blockIdx.x & 15;
    const float* __restrict__ P =
        ((db >> 2) ? p2 : p1) + (size_t)(db & 3) * NPTS * 3;
#pragma unroll
    for (int k = 0; k < 2; k++) {
        int i = chunk * 512 + threadIdx.x + k * 256;
        float x = P[3 * i], y = P[3 * i + 1], z = P[3 * i + 2];
        int pos = atomicAdd(&g_coff[db][bucket(x)], 1);
        g_pts[db][pos] = make_float4(x, y, z, x * x + y * y + z * z);
    }
}

// ---- Pass A: per-tile + per-warp d2 bounds; 2 blocks per query tile ----------
__global__ __launch_bounds__(128)
void bound_kernel() {
    __shared__ __align__(16) float4 s_w[256];    // 4 KB window
    __shared__ float sred[4];
    const int tid = threadIdx.x, lane = tid & 31, wid = tid >> 5;
    const int qt = blockIdx.x >> 1, sub = blockIdx.x & 1, db = blockIdx.y;
    const float4* __restrict__ Q = g_pts[db];
    const float4* __restrict__ T = g_pts[db ^ 4];

    const int ws = min(max(qt * TQ + TQ / 2 - 128, 0), NPTS - 256);
    s_w[tid]       = T[ws + tid];                // coalesced stage
    s_w[tid + 128] = T[ws + tid + 128];
    const float4 q = Q[qt * TQ + sub * 128 + tid];
    const float m2x = -2.f * q.x, m2y = -2.f * q.y, m2z = -2.f * q.z;
    __syncthreads();

    float a0 = BIG, a1 = BIG, a2 = BIG, a3 = BIG;
#pragma unroll 4
    for (int j = 0; j < 256; j += 4) {           // warp-uniform LDS broadcast
        float4 t0 = s_w[j], t1 = s_w[j + 1], t2 = s_w[j + 2], t3 = s_w[j + 3];
        a0 = fminf(a0, fmaf(m2x, t0.x, fmaf(m2y, t0.y, fmaf(m2z, t0.z, t0.w))));
        a1 = fminf(a1, fmaf(m2x, t1.x, fmaf(m2y, t1.y, fmaf(m2z, t1.z, t1.w))));
        a2 = fminf(a2, fmaf(m2x, t2.x, fmaf(m2y, t2.y, fmaf(m2z, t2.z, t2.w))));
        a3 = fminf(a3, fmaf(m2x, t3.x, fmaf(m2y, t3.y, fmaf(m2z, t3.z, t3.w))));
    }
    float dm = fmaxf(fminf(fminf(a0, a1), fminf(a2, a3)) + q.w, 0.0f);

#pragma unroll
    for (int o = 16; o; o >>= 1) dm = fmaxf(dm, __shfl_xor_sync(FULLMASK, dm, o));
    if (lane == 0) {
        sred[wid] = dm;
        g_dmaxw[db][qt * 8 + sub * 4 + wid] = dm;    // per-32-query-warp bound
    }
    __syncthreads();
    if (tid == 0) {
        float m = fmaxf(fmaxf(sred[0], sred[1]), fmaxf(sred[2], sred[3]));
        atomicMax(&g_dmax[db][qt], __float_as_int(m));   // m >= 0: int-cmp valid
    }
}

// ---- Pass B: FFMA2 tile loop; block + warp pruning BEFORE staging ------------
__global__ __launch_bounds__(PB_THREADS)
void tile_kernel() {
    const int qt = blockIdx.x >> 5, ts = blockIdx.x & 31;
    const int db = blockIdx.y;
    const float4* __restrict__ Q = g_pts[db];
    const float4* __restrict__ T = g_pts[db ^ 4];

    const float tlo = T[ts * TT].x, thi = T[ts * TT + TT - 1].x;

    // Block-level prune (endpoint x's; 2*EPSB covers bucket disorder).
    {
        const float qlo = Q[qt * TQ].x, qhi = Q[qt * TQ + TQ - 1].x;
        const float gap = fmaxf(0.f, fmaxf(tlo - qhi, qlo - thi) - 2.0f * EPSB);
        if (gap * gap > __int_as_float(g_dmax[db][qt]) * 1.0001f + 1e-6f) return;
    }

    const int tid = threadIdx.x, lane = tid & 31, wid = tid >> 5;

    // Warp owns 64 contiguous queries: q0 = 2*tid, q1 = 2*tid+1.
    const float4 qa = Q[qt * TQ + 2 * tid];
    const float4 qb = Q[qt * TQ + 2 * tid + 1];

    // Warp-level certificate BEFORE staging (exact query x-range via shuffles).
    bool wsurvive;
    {
        float xmn = fminf(qa.x, qb.x), xmx = fmaxf(qa.x, qb.x);
#pragma unroll
        for (int o = 16; o; o >>= 1) {
            xmn = fminf(xmn, __shfl_xor_sync(FULLMASK, xmn, o));
            xmx = fmaxf(xmx, __shfl_xor_sync(FULLMASK, xmx, o));
        }
        const float wd = fmaxf(g_dmaxw[db][qt * 8 + wid * 2],
                               g_dmaxw[db][qt * 8 + wid * 2 + 1]);
        const float gap = fmaxf(0.f, fmaxf(tlo - xmx, xmn - thi) - EPSB);
        wsurvive = !(gap * gap > wd * 1.0001f + 1e-6f);
    }
    if (!__syncthreads_or((int)wsurvive)) return;    // nobody needs this tile

    // Stage target tile: per pair -> (n0,n1,n2,cc) packed f32x2 (all threads).
    __shared__ __align__(16) ull s_t[TT / 2][4];     // 4 KB packed pairs
    {
        float4 ta = T[ts * TT + 2 * tid];
        float4 tc = T[ts * TT + 2 * tid + 1];
        ulonglong2* d = (ulonglong2*)s_t[tid];
        d[0] = make_ulonglong2(pack2(-2.0f * ta.x, -2.0f * tc.x),
                               pack2(-2.0f * ta.y, -2.0f * tc.y));
        d[1] = make_ulonglong2(pack2(-2.0f * ta.z, -2.0f * tc.z),
                               pack2(ta.w, tc.w));
    }
    __syncthreads();
    if (!wsurvive) return;                           // certified warps exit

    const ull qx0 = pack2(qa.x, qa.x), qy0 = pack2(qa.y, qa.y), qz0 = pack2(qa.z, qa.z);
    const ull qx1 = pack2(qb.x, qb.x), qy1 = pack2(qb.y, qb.y), qz1 = pack2(qb.z, qb.z);
    float ma0 = BIG, mb0 = BIG, ma1 = BIG, mb1 = BIG;

    const ulonglong2* sm = (const ulonglong2*)&s_t[0][0];
#pragma unroll 4
    for (int j = 0; j < TT / 2; j++) {
        ulonglong2 v0 = sm[2 * j];       // (n0,n1) LDS.128 broadcast
        ulonglong2 v1 = sm[2 * j + 1];   // (n2,cc)
        step(ma0, mb0, qx0, qy0, qz0, v0.x, v0.y, v1.x, v1.y);
        step(ma1, mb1, qx1, qy1, qz1, v0.x, v0.y, v1.x, v1.y);
    }

    unsigned* gk = g_key + db * NPTS + qt * TQ;
    atomicMax(&gk[2 * tid],     enckey(fminf(ma0, mb0)));
    atomicMax(&gk[2 * tid + 1], enckey(fminf(ma1, mb1)));
}

// ---- Finish: add |q|^2, reduce, atomicAdd; reset keys ------------------------
__global__ __launch_bounds__(256)
void finish_kernel(float* __restrict__ out) {
    const int gid = blockIdx.x * 256 + threadIdx.x;
    const int db = gid >> 13, qi = gid & (NPTS - 1);
    float v = deckey(g_key[gid]) + g_pts[db][qi].w;
    g_key[gid] = 0u;

    __shared__ float sred[8];
#pragma unroll
    for (int o = 16; o; o >>= 1) v += __shfl_down_sync(FULLMASK, v, o);
    if ((threadIdx.x & 31) == 0) sred[threadIdx.x >> 5] = v;
    __syncthreads();
    if (threadIdx.x == 0) {
        float t = 0.f;
#pragma unroll
        for (int i = 0; i < 8; i++) t += sred[i];
        atomicAdd(out, t);
    }
}

extern "C" void kernel_launch(void* const* d_in, const int* in_sizes, int n_in,
                              void* d_out, int out_size) {
    const float* p1 = (const float*)d_in[0];
    const float* p2 = (const float*)d_in[1];
    float* out = (float*)d_out;

    hist_kernel<<<128, 256>>>(p1, p2);
    scan_kernel<<<8, 1024>>>(out);
    scatter_kernel<<<128, 256>>>(p1, p2);
    bound_kernel<<<dim3(NQT * 2, 8), 128>>>();
    tile_kernel<<<dim3(NQT * NTS, 8), PB_THREADS>>>();
    finish_kernel<<<TOTQ / 256, 256>>>(out);
}